// round 14
// baseline (speedup 1.0000x reference)
#include <cuda_runtime.h>
#include <math.h>

// Problem constants (fixed by the reference)
#define B_DIM 2
#define L_DIM 2048
#define V_DIM 32001
#define ROWS (B_DIM * L_DIM)                       // 4096
#define ROW_BYTES ((long long)V_DIM * 4)           // 128004
#define REV_BYTES (524304384LL)                    // ROWS*V_DIM*4

// Fill split: memset covers [0, SPLIT), kernel covers [SPLIT, REV_BYTES).
// 192 chunks x 128128 B = 24600576 B (kernel slice), both 128B-aligned.
#define CHUNK_BYTES 128128LL
#define G_FILL 192
#define KERNEL_SLICE (G_FILL * CHUNK_BYTES)        // 24600576
#define SPLIT_BYTES (REV_BYTES - KERNEL_SLICE)     // 499703808, 128B-aligned

#define G_LOGIC 16                                 // logic blocks (4096 threads)
#define G_TOTAL (G_LOGIC + G_FILL)                 // 208 blocks

struct alignas(32) F8 { float4 a, b; };

__device__ __forceinline__ float gumbel_noise(float u) {
    const float GEPS = 1e-6f;
    return GEPS - logf(GEPS + (1.0f - GEPS) * u);
}

__device__ __forceinline__ bool is_mask_tok(int x) {
    return x == -1 || x == (V_DIM - 1);
}

// Runs AFTER the memset node (stream-ordered):
//   blocks [0, G_LOGIC): row logic. x_new for every row; masked rows get the
//     full rev-row + gumbel sample written directly (memset region already
//     zeroed -> safe to overwrite; kernel-slice region skipped by fill blocks
//     -> no race).
//   blocks [G_LOGIC, G_TOTAL): zero-fill of rev[SPLIT, REV) with 128B-aligned
//     32B stores, skipping bytes of masked rows (<=3 uniform xt loads/chunk).
//   The fill work (~3.5us) hides under the kernel launch ramp, so this node
//   costs barely more than the bare logic kernel while shrinking the memset.
__global__ __launch_bounds__(256)
void fused_tail_kernel(const float* __restrict__ outp,   // [B,L,V]
                       const int* __restrict__ xt,       // [B,L]
                       const float* __restrict__ t,      // [B]
                       const float* __restrict__ step_p, // [1]
                       const float* __restrict__ u,      // [B,L,V]
                       float* __restrict__ x_new,        // [B*L]
                       float* __restrict__ rev)          // [B,L,V]
{
    const int tid = threadIdx.x;
    const int mask_tok = V_DIM - 1;
    const float EPS = 1e-3f;

    if (blockIdx.x >= G_LOGIC) {
        // ---- tail fill: one contiguous 128B-aligned chunk per block ----
        const long long fb = blockIdx.x - G_LOGIC;
        const long long byte0 = SPLIT_BYTES + fb * CHUNK_BYTES;
        long long byte1 = byte0 + CHUNK_BYTES;
        if (byte1 > REV_BYTES) byte1 = REV_BYTES;

        const int row0 = (int)(byte0 / ROW_BYTES);
        int row1 = (int)((byte1 - 1) / ROW_BYTES);
        if (row1 > ROWS - 1) row1 = ROWS - 1;

        bool any_mask = false;
        for (int r = row0; r <= row1; r++)          // <=3 uniform loads
            any_mask |= is_mask_tok(xt[r]);

        const long long b8_0 = byte0 / 32, b8_1 = byte1 / 32;
        if (!any_mask) {
            // fast path: contiguous 32B stores, all warp segments line-aligned
            F8 z; z.a = make_float4(0.f, 0.f, 0.f, 0.f); z.b = z.a;
            F8* __restrict__ p = (F8*)rev;
            for (long long i = b8_0 + tid; i < b8_1; i += 256) p[i] = z;
        } else {
            // rare path: elementwise, skipping floats owned by masked rows
            const long long f0 = byte0 >> 2, f1 = byte1 >> 2;
            for (long long i = f0 + tid; i < f1; i += 256) {
                const int r = (int)((i * 4) / ROW_BYTES);
                if (!is_mask_tok(xt[r])) rev[i] = 0.0f;
            }
        }
        return;
    }

    // ---- row logic: thread-per-row ----
    const int row = blockIdx.x * 256 + tid;   // 0..4095

    __shared__ int s_count;
    __shared__ int s_rows[256];
    if (tid == 0) s_count = 0;
    __syncthreads();

    int x = xt[row];
    if (x == -1) x = mask_tok;

    if (x != mask_tok) {
        // rev row is exactly zero; argmax of xt_prob/gnoise is x itself.
        x_new[row] = (float)x;
    } else {
        int slot = atomicAdd(&s_count, 1);
        s_rows[slot] = row;
    }
    __syncthreads();

    const int cnt = s_count;
    if (cnt == 0) return;

    // ---- cooperative heavy path: full rev row + gumbel sample ----
    __shared__ float s_sum[256];
    __shared__ float s_val[256];
    __shared__ int   s_idx[256];

    const float step = *step_p;

    for (int m = 0; m < cnt; m++) {
        const int mrow = s_rows[m];
        const int b = mrow / L_DIM;
        const float sigma = (1.0f - EPS) / (1.0f - (1.0f - EPS) * t[b]);

        const float* __restrict__ orow = outp + (long long)mrow * V_DIM;
        const float* __restrict__ urow = u    + (long long)mrow * V_DIM;
        float* __restrict__       rrow = rev  + (long long)mrow * V_DIM;

        float sum = 0.0f;
        float best_v = -INFINITY;
        int   best_i = V_DIM;

        for (int v = tid; v < V_DIM; v += 256) {
            if (v == mask_tok) continue;
            float s = expf(orow[v]);
            sum += s;
            float r = sigma * s;          // off-diagonal rev_rate
            rrow[v] = r;                  // fill blocks skip this row
            float g = gumbel_noise(urow[v]);
            float ratio = (step * r) / g;
            if (ratio > best_v || (ratio == best_v && v < best_i)) {
                best_v = ratio;
                best_i = v;
            }
        }

        s_sum[tid] = sum;
        s_val[tid] = best_v;
        s_idx[tid] = best_i;
        __syncthreads();

        for (int off = 128; off > 0; off >>= 1) {
            if (tid < off) {
                s_sum[tid] += s_sum[tid + off];
                float ov = s_val[tid + off];
                int   oi = s_idx[tid + off];
                if (ov > s_val[tid] || (ov == s_val[tid] && oi < s_idx[tid])) {
                    s_val[tid] = ov;
                    s_idx[tid] = oi;
                }
            }
            __syncthreads();
        }

        if (tid == 0) {
            float rd = sigma * (-s_sum[0]);        // diagonal rev_rate
            rrow[mask_tok] = rd;
            float prob = 1.0f + step * rd;         // oh=1 at diagonal
            float g = gumbel_noise(urow[mask_tok]);
            float ratio = prob / g;
            int res = s_idx[0];
            if (ratio > s_val[0]) res = mask_tok;  // tie -> lower index wins
            x_new[mrow] = (res == mask_tok) ? -1.0f : (float)res;
        }
        __syncthreads();
    }
}

extern "C" void kernel_launch(void* const* d_in, const int* in_sizes, int n_in,
                              void* d_out, int out_size) {
    const float* outp   = (const float*)d_in[0]; // [B,L,V] f32
    const int*   xt     = (const int*)  d_in[1]; // [B,L]   i32
    const float* t      = (const float*)d_in[2]; // [B]     f32
    const float* step_p = (const float*)d_in[3]; // scalar  f32
    const float* u      = (const float*)d_in[4]; // [B,L,V] f32

    float* x_new = (float*)d_out;                  // first B*L elements
    float* rev   = (float*)d_out + ROWS;           // then B*L*V elements

    // Bulk of the compulsory zero write at memset bandwidth (~7.45 TB/s).
    cudaMemsetAsync(rev, 0, (size_t)SPLIT_BYTES);

    // Tail fill (24.6 MB) + row logic in one kernel; the fill hides under the
    // kernel's launch ramp, so this node costs ~the same as the logic alone.
    fused_tail_kernel<<<G_TOTAL, 256>>>(outp, xt, t, step_p, u, x_new, rev);
}

// round 15
// speedup vs baseline: 1.0337x; 1.0337x over previous
#include <cuda_runtime.h>
#include <math.h>

// Problem constants (fixed by the reference)
#define B_DIM 2
#define L_DIM 2048
#define V_DIM 32001
#define ROWS (B_DIM * L_DIM)          // 4096 = 16 blocks x 256 threads

__device__ __forceinline__ float gumbel_noise(float u) {
    const float GEPS = 1e-6f;
    return GEPS - logf(GEPS + (1.0f - GEPS) * u);
}

// Runs CONCURRENTLY with the memset (parallel capture branch):
//  - fast path writes only x_new (first 16KB of d_out) — disjoint from the
//    memset region, safe under concurrency.
//  - masked rows (~0 of 4096): before overwriting a rev row, spin until the
//    whole row reads bitwise zero. Pre-memset the row holds 0xAA poison
//    (first call) or the previous replay's strictly nonzero sigma*exp values,
//    so all-zero implies the memset has already written every byte of it;
//    our subsequent stores can then never be clobbered.
__global__ void row_logic_kernel(const float* __restrict__ outp,   // [B,L,V]
                                 const int* __restrict__ xt,       // [B,L]
                                 const float* __restrict__ t,      // [B]
                                 const float* __restrict__ step_p, // [1]
                                 const float* __restrict__ u,      // [B,L,V]
                                 float* __restrict__ x_new,        // [B*L]
                                 float* __restrict__ rev)          // [B,L,V]
{
    const int tid = threadIdx.x;
    const int row = blockIdx.x * blockDim.x + tid;   // 0..4095
    const int mask_tok = V_DIM - 1;

    __shared__ int s_count;
    __shared__ int s_rows[256];

    if (tid == 0) s_count = 0;
    __syncthreads();

    int x = xt[row];
    if (x == -1) x = mask_tok;

    if (x != mask_tok) {
        x_new[row] = (float)x;      // concurrent-safe: disjoint from rev
    } else {
        int slot = atomicAdd(&s_count, 1);
        s_rows[slot] = row;
    }
    __syncthreads();

    const int cnt = s_count;
    if (cnt == 0) return;           // common case: exit, fully overlapped

    __shared__ float s_sum[256];
    __shared__ float s_val[256];
    __shared__ int   s_idx[256];

    const float EPS  = 1e-3f;
    const float step = *step_p;

    for (int m = 0; m < cnt; m++) {
        const int mrow = s_rows[m];
        const int b = mrow / L_DIM;
        const float sigma = (1.0f - EPS) / (1.0f - (1.0f - EPS) * t[b]);

        const float* __restrict__ orow = outp + (long long)mrow * V_DIM;
        const float* __restrict__ urow = u    + (long long)mrow * V_DIM;
        float* __restrict__       rrow = rev  + (long long)mrow * V_DIM;

        // ---- ordering spin: wait until memset has zeroed this row ----
        for (int v = tid; v < V_DIM; v += 256) {
            volatile float* p = (volatile float*)(rrow + v);
            while (*p != 0.0f) { }
        }
        __syncthreads();

        float sum = 0.0f;
        float best_v = -INFINITY;
        int   best_i = V_DIM;   // larger than any real index

        for (int v = tid; v < V_DIM; v += 256) {
            if (v == mask_tok) continue;
            float s = expf(orow[v]);
            sum += s;
            float r = sigma * s;          // rev_rate off-diagonal
            rrow[v] = r;
            float g = gumbel_noise(urow[v]);
            float ratio = (step * r) / g; // xt_prob[v] = 0 + step*rev
            if (ratio > best_v || (ratio == best_v && v < best_i)) {
                best_v = ratio;
                best_i = v;
            }
        }

        s_sum[tid] = sum;
        s_val[tid] = best_v;
        s_idx[tid] = best_i;
        __syncthreads();

        for (int off = 128; off > 0; off >>= 1) {
            if (tid < off) {
                s_sum[tid] += s_sum[tid + off];
                float ov = s_val[tid + off];
                int   oi = s_idx[tid + off];
                if (ov > s_val[tid] || (ov == s_val[tid] && oi < s_idx[tid])) {
                    s_val[tid] = ov;
                    s_idx[tid] = oi;
                }
            }
            __syncthreads();
        }

        if (tid == 0) {
            float total = s_sum[0];
            float rd = sigma * (-total);           // diagonal rev_rate
            rrow[mask_tok] = rd;
            float prob = 1.0f + step * rd;         // oh=1 at diagonal
            float g = gumbel_noise(urow[mask_tok]);
            float ratio = prob / g;
            int res = s_idx[0];
            float bv = s_val[0];
            // diagonal index is V-1 (largest), so on a tie off-diagonal wins
            if (ratio > bv) res = mask_tok;
            x_new[mrow] = (res == mask_tok) ? -1.0f : (float)res;
        }
        __syncthreads();
    }
}

extern "C" void kernel_launch(void* const* d_in, const int* in_sizes, int n_in,
                              void* d_out, int out_size) {
    const float* outp   = (const float*)d_in[0]; // [B,L,V] f32
    const int*   xt     = (const int*)  d_in[1]; // [B,L]   i32
    const float* t      = (const float*)d_in[2]; // [B]     f32
    const float* step_p = (const float*)d_in[3]; // scalar  f32
    const float* u      = (const float*)d_in[4]; // [B,L,V] f32

    float* x_new = (float*)d_out;                  // first B*L elements
    float* rev   = (float*)d_out + ROWS;           // then B*L*V elements

    // Fork a parallel capture branch so the logic kernel overlaps the memset.
    cudaStream_t side;
    cudaStreamCreateWithFlags(&side, cudaStreamNonBlocking);
    cudaEvent_t e_fork, e_join;
    cudaEventCreateWithFlags(&e_fork, cudaEventDisableTiming);
    cudaEventCreateWithFlags(&e_join, cudaEventDisableTiming);

    cudaEventRecord(e_fork, 0);
    cudaStreamWaitEvent(side, e_fork, 0);

    // Branch A (main stream): compulsory 524 MB zero at ~7.7 TB/s.
    cudaMemsetAsync(rev, 0, (size_t)ROWS * V_DIM * sizeof(float), 0);

    // Branch B (side stream): row logic, fully overlapped.
    row_logic_kernel<<<ROWS / 256, 256, 0, side>>>(outp, xt, t, step_p, u,
                                                   x_new, rev);

    cudaEventRecord(e_join, side);
    cudaStreamWaitEvent(0, e_join, 0);

    cudaEventDestroy(e_fork);
    cudaEventDestroy(e_join);
    cudaStreamDestroy(side);
}